// round 16
// baseline (speedup 1.0000x reference)
#include <cuda_runtime.h>
#include <cuda_fp16.h>
#include <cstdint>

#define Bn   128
#define Sn   512
#define Ln   64
#define NPAIRS ((Bn-1)*Sn)       // 65024
#define NBLK2 (NPAIRS/256)       // 254 blocks, two 128-pair tiles each
#define EP   132                 // est row pitch (h2 units)
#define TP2  68                  // sT2 row pitch (h2 units)

#define LOG2E 1.4426950408889634f
#define LN2f  0.6931471805599453f

// dynamic smem layout (bytes)
#define SO_ST    0               // 32*68*4  = 8704
#define SO_EST   8704            // 32*132*4 = 16896
#define SO_STAGE 25600           // 32768 (128 rows x 64 f32)
#define SO_FLAGS 58368           // 256 f32
#define SO_SSC   59392           // 8 f32
#define SO_SCNT  59424           // 4 int
#define SO_SLAST 59440
#define SMEM_TOTAL 59520

// Zero-initialized at module load; finalizer resets after use (replay safe).
__device__ float    g_alpha[Ln];
__device__ double   g_score;
__device__ unsigned g_done;

__device__ __forceinline__ float ex2f(float x){ float y; asm("ex2.approx.f32 %0, %1;" : "=f"(y) : "f"(x)); return y; }
__device__ __forceinline__ float lg2f_(float x){ float y; asm("lg2.approx.f32 %0, %1;" : "=f"(y) : "f"(x)); return y; }
__device__ __forceinline__ unsigned pk2(float lo, float hi){
    unsigned r; asm("cvt.rn.f16x2.f32 %0, %1, %2;" : "=r"(r) : "f"(hi), "f"(lo)); return r;
}
__device__ __forceinline__ unsigned ex2h2(unsigned x){
    unsigned r; asm("ex2.approx.f16x2 %0, %1;" : "=r"(r) : "r"(x)); return r;
}
__device__ __forceinline__ void hfma2(unsigned& d, unsigned a, unsigned b){
    asm("fma.rn.f16x2 %0, %1, %2, %0;" : "+r"(d) : "r"(a), "r"(b));
}
__device__ __forceinline__ float h2sum(unsigned h){
    __half2 v = *reinterpret_cast<__half2*>(&h);
    float2 f = __half22float2(v);
    return f.x + f.y;
}
__device__ __forceinline__ unsigned smem_u32(const void* p){
    unsigned a; asm("{ .reg .u64 t; cvta.to.shared.u64 t, %1; cvt.u32.u64 %0, t; }" : "=r"(a) : "l"(p)); return a;
}
__device__ __forceinline__ void cpa16(unsigned dst, const void* src){
    asm volatile("cp.async.cg.shared.global [%0], [%1], 16;" :: "r"(dst), "l"(src) : "memory");
}
__device__ __forceinline__ void cpa_commit(){ asm volatile("cp.async.commit_group;" ::: "memory"); }
__device__ __forceinline__ void cpa_wait0(){ asm volatile("cp.async.wait_group 0;" ::: "memory"); }

// One 128-pair tile mainloop (HFMA2, packed over j-pairs); csum accumulates.
__device__ __forceinline__ void tile_main(const unsigned* __restrict__ sT2,
                                          const unsigned* __restrict__ est,
                                          const float* __restrict__ flg,
                                          int i4, int pg, float csum[4])
{
    unsigned acc[4][8];
    #pragma unroll
    for (int k = 0; k < 4; ++k)
        #pragma unroll
        for (int m = 0; m < 8; ++m) acc[k][m] = 0u;

    const uint4* sTv = (const uint4*)sT2;       // [j2*17 + i4]
    const uint4* eV  = (const uint4*)est;       // [j2*33 + pg*2]

    #pragma unroll 8
    for (int j2 = 0; j2 < 32; ++j2){
        uint4 tv = sTv[j2*17 + i4];
        uint4 ea = eV[j2*33 + pg*2];
        uint4 eb = eV[j2*33 + pg*2 + 1];
        unsigned tp[4] = {tv.x, tv.y, tv.z, tv.w};
        unsigned ep[8] = {ea.x, ea.y, ea.z, ea.w, eb.x, eb.y, eb.z, eb.w};
        #pragma unroll
        for (int k = 0; k < 4; ++k){
            #pragma unroll
            for (int m = 0; m < 8; ++m) hfma2(acc[k][m], tp[k], ep[m]);
        }
    }
    bool f[8];
    #pragma unroll
    for (int m = 0; m < 8; ++m) f[m] = flg[pg*8 + m] != 0.0f;
    #pragma unroll
    for (int k = 0; k < 4; ++k){
        float a0 = f[0] ? h2sum(acc[k][0]) : 1.0f;
        float a1 = f[1] ? h2sum(acc[k][1]) : 1.0f;
        float a2 = f[2] ? h2sum(acc[k][2]) : 1.0f;
        float a3 = f[3] ? h2sum(acc[k][3]) : 1.0f;
        float b0 = f[4] ? h2sum(acc[k][4]) : 1.0f;
        float b1 = f[5] ? h2sum(acc[k][5]) : 1.0f;
        float b2 = f[6] ? h2sum(acc[k][6]) : 1.0f;
        float b3 = f[7] ? h2sum(acc[k][7]) : 1.0f;
        csum[k] += lg2f_((a0*a1)*(a2*a3)) + lg2f_((b0*b1)*(b2*b3));
    }
}

// ---------------------------------------------------------------------------
// Mega kernel: 254 blocks x 256 threads; two pipelined 128-pair tiles each.
// ---------------------------------------------------------------------------
__global__ __launch_bounds__(256, 2) void mega_kernel(
    const float* __restrict__ emit,  const int* __restrict__ labels,
    const int*   __restrict__ mask,  const float* __restrict__ trans,
    const float* __restrict__ strans,const float* __restrict__ etrans,
    float* __restrict__ out)
{
    extern __shared__ char smem[];
    unsigned* sT2   = (unsigned*)(smem + SO_ST);
    unsigned* est   = (unsigned*)(smem + SO_EST);
    float*    stage = (float*)   (smem + SO_STAGE);
    float*    flags = (float*)   (smem + SO_FLAGS);
    float*    ssc   = (float*)   (smem + SO_SSC);
    int*      scnt  = (int*)     (smem + SO_SCNT);
    unsigned* slast = (unsigned*)(smem + SO_SLAST);

    const int t  = threadIdx.x;
    const int bx = blockIdx.x;
    const int P0 = bx * 256;          // pair base (2 tiles of 128)
    const int i4 = t & 15;
    const int pg = t >> 4;
    const unsigned stg = smem_u32(stage);

    // ======== issue cp.async for tile 0 immediately ========
    const float4* e4 = (const float4*)(emit + (size_t)(P0 + Sn)*Ln);  // 4096 float4 = 2 tiles
    #pragma unroll
    for (int it = 0; it < 8; ++it){
        int v = t + it*256;
        cpa16(stg + v*16, e4 + v);
    }
    cpa_commit();

    // ======== front-issue scattered score gathers ========
    int gp = P0 + Sn + t;             // this block's pair (both tiles)
    int l  = labels[gp];
    int lp = labels[gp - 1];
    float em_v = emit[(size_t)gp*Ln + l];
    float tr_v = trans[lp*Ln + l];
    int   mk   = mask[gp];
    float v0 = 0.f;
    if (bx < 2){
        int g2 = bx*256 + t;          // b=0 rows 0..511
        int l2 = labels[g2];
        int g2m = (g2 > 0) ? g2 - 1 : 0;
        float e2 = emit[(size_t)g2*Ln + l2];
        float t2 = trans[labels[g2m]*Ln + l2];
        if (mask[g2]){ v0 = e2; if (g2 & 511) v0 += t2; }
    }
    int4 mker = make_int4(0,0,0,0);
    if (bx < Bn && t >= 128) mker = ((const int4*)(mask + bx*Sn))[t - 128];

    // ======== sT2 build ========
    #pragma unroll
    for (int it = 0; it < 8; ++it){
        int o = t + it*256;
        int i = o >> 5, j2 = o & 31;
        float2 tv = *(const float2*)(trans + i*64 + 2*j2);
        sT2[j2*TP2 + i] = ex2h2(pk2(tv.x*LOG2E, tv.y*LOG2E));
    }
    flags[t] = mk ? 1.0f : 0.0f;      // flags[t] <-> pair P0+t (both tiles)

    // ======== wait tile-0 copy, fill est0 ========
    cpa_wait0();
    __syncthreads();
    #pragma unroll
    for (int it = 0; it < 8; ++it){
        int v = t + it*256;           // 0..2047
        float4 x = ((const float4*)stage)[v];
        int p  = v >> 4;
        int j2 = (v & 15) * 2;
        est[(j2  )*EP + p] = ex2h2(pk2(x.x*LOG2E, x.y*LOG2E));
        est[(j2+1)*EP + p] = ex2h2(pk2(x.z*LOG2E, x.w*LOG2E));
    }
    __syncthreads();                  // est0 ready; stage free

    // ======== issue cp.async for tile 1 (hidden under mainloop0) ========
    #pragma unroll
    for (int it = 0; it < 8; ++it){
        int v = t + it*256;
        cpa16(stg + v*16, e4 + 2048 + v);
    }
    cpa_commit();

    // ======== mainloop tile 0 ========
    float csum[4] = {0.f, 0.f, 0.f, 0.f};
    tile_main(sT2, est, flags, i4, pg, csum);

    // ======== fill est1, mainloop tile 1 ========
    cpa_wait0();
    __syncthreads();                  // mainloop0 reads done + copy complete
    #pragma unroll
    for (int it = 0; it < 8; ++it){
        int v = t + it*256;
        float4 x = ((const float4*)stage)[v];
        int p  = v >> 4;
        int j2 = (v & 15) * 2;
        est[(j2  )*EP + p] = ex2h2(pk2(x.x*LOG2E, x.y*LOG2E));
        est[(j2+1)*EP + p] = ex2h2(pk2(x.z*LOG2E, x.w*LOG2E));
    }
    __syncthreads();
    tile_main(sT2, est, flags + 128, i4, pg, csum);

    // ======== score consume + reduce ========
    {
        float v = v0;
        if (mk){
            v += em_v;
            if (gp & 511) v += tr_v;
        }
        #pragma unroll
        for (int o = 16; o; o >>= 1) v += __shfl_down_sync(0xffffffffu, v, o);
        if ((t & 31) == 0) ssc[t >> 5] = v;
    }
    if (bx < Bn && t >= 128){
        int cnt = (mker.x!=0) + (mker.y!=0) + (mker.z!=0) + (mker.w!=0);
        #pragma unroll
        for (int o = 16; o; o >>= 1) cnt += __shfl_down_sync(0xffffffffu, cnt, o);
        if (((t - 128) & 31) == 0) scnt[(t - 128) >> 5] = cnt;
    }

    __syncthreads();
    float* red = (float*)est;
    #pragma unroll
    for (int k = 0; k < 4; ++k) red[pg*64 + i4*4 + k] = csum[k];
    __syncthreads();

    if (t == 0){
        double tot = 0.0;
        #pragma unroll
        for (int i = 0; i < 8; ++i) tot += (double)ssc[i];
        if (bx < Bn){
            int c = scnt[0] + scnt[1] + scnt[2] + scnt[3];
            int end = c - 1; if (end < 0) end = 0;
            const int* lab = labels + bx*Sn;
            tot += (double)strans[lab[0]] + (double)etrans[lab[end]];
        }
        atomicAdd(&g_score, tot);
    }
    if (t < Ln){
        float s = 0.f;
        #pragma unroll
        for (int gi = 0; gi < 16; ++gi) s += red[gi*64 + t];
        atomicAdd(&g_alpha[t], s * LN2f);
    }

    // ======== last-block finalize + state reset ========
    __threadfence();
    __syncthreads();
    if (t == 0){
        unsigned prev = atomicAdd(&g_done, 1u);
        *slast = (prev == NBLK2 - 1) ? 1u : 0u;
    }
    __syncthreads();
    if (*slast){
        float a = -1e30f;
        if (t < Ln) a = g_alpha[t] + emit[t];      // + emit[0,0,:]
        float m = a;
        #pragma unroll
        for (int o = 16; o; o >>= 1) m = fmaxf(m, __shfl_xor_sync(0xffffffffu, m, o));
        if ((t & 31) == 0) red[t >> 5] = m;
        __syncthreads();
        m = fmaxf(fmaxf(fmaxf(red[0], red[1]), fmaxf(red[2], red[3])),
                  fmaxf(fmaxf(red[4], red[5]), fmaxf(red[6], red[7])));
        float e = (t < Ln) ? ex2f((a - m) * LOG2E) : 0.f;
        #pragma unroll
        for (int o = 16; o; o >>= 1) e += __shfl_xor_sync(0xffffffffu, e, o);
        if ((t & 31) == 0) red[8 + (t >> 5)] = e;
        __syncthreads();
        if (t == 0){
            float es = 0.f;
            #pragma unroll
            for (int i = 0; i < 8; ++i) es += red[8 + i];
            double logZ = (double)m + (double)(LN2f * lg2f_(es));
            out[0] = (float)((logZ - g_score) / (double)Bn);
        }
        __syncthreads();
        if (t < Ln)  g_alpha[t] = 0.0f;
        if (t == 0){ g_score = 0.0; g_done = 0u; }
    }
}

// ---------------------------------------------------------------------------
extern "C" void kernel_launch(void* const* d_in, const int* in_sizes, int n_in,
                              void* d_out, int out_size)
{
    const float* emit   = (const float*)d_in[0];
    const int*   labels = (const int*)d_in[1];
    const int*   mask   = (const int*)d_in[2];
    const float* trans  = (const float*)d_in[3];
    const float* strans = (const float*)d_in[4];
    const float* etrans = (const float*)d_in[5];
    float* out = (float*)d_out;

    cudaFuncSetAttribute(mega_kernel, cudaFuncAttributeMaxDynamicSharedMemorySize, SMEM_TOTAL);
    mega_kernel<<<NBLK2, 256, SMEM_TOTAL>>>(emit, labels, mask, trans, strans, etrans, out);
}